// round 6
// baseline (speedup 1.0000x reference)
#include <cuda_runtime.h>
#include <stdint.h>

// ---------------------------------------------------------------------------
// Problem constants
// ---------------------------------------------------------------------------
static const int kB  = 1024;   // batch
static const int kIN = 784;    // input dim
static const int kE  = 256;    // embed dim
static const int kC  = 10;     // classes
static const int kAD = 3;      // ADIM
static const int kBR = 4;      // BRAIN
static const int kNB = 64;     // blocks
static const int kJ  = 4;      // NJUMPS
static const int TS  = 8;      // samples per tile
static const int KOUT = kAD * kBR;  // 12

// ---------------------------------------------------------------------------
// Scratch (device globals -- no cudaMalloc allowed)
// ---------------------------------------------------------------------------
__device__ float g_state[kB * kE];
__device__ float g_init [kB * kE];
__device__ int   g_done [kB];
__device__ int   g_cnt  [kJ + 1][kNB];
__device__ int   g_list [kJ + 1][kNB][kB];

// ---------------------------------------------------------------------------
// Threefry-2x32-20 (KAT: key(0,0) ctr(0,0) -> 0x6b200159, 0x99ba4efe)
// ---------------------------------------------------------------------------
__host__ __device__ inline void tf2x32(uint32_t k0, uint32_t k1,
                                       uint32_t x0, uint32_t x1,
                                       uint32_t* o0, uint32_t* o1)
{
    uint32_t ks2 = k0 ^ k1 ^ 0x1BD11BDAu;
    x0 += k0; x1 += k1;
#define TF_ROT(v, d) (((v) << (d)) | ((v) >> (32 - (d))))
#define TF_R4(a, b, c, d)                                    \
    { x0 += x1; x1 = TF_ROT(x1, a); x1 ^= x0;                \
      x0 += x1; x1 = TF_ROT(x1, b); x1 ^= x0;                \
      x0 += x1; x1 = TF_ROT(x1, c); x1 ^= x0;                \
      x0 += x1; x1 = TF_ROT(x1, d); x1 ^= x0; }
    TF_R4(13, 15, 26, 6)   x0 += k1;  x1 += ks2 + 1u;
    TF_R4(17, 29, 16, 24)  x0 += ks2; x1 += k0  + 2u;
    TF_R4(13, 15, 26, 6)   x0 += k0;  x1 += k1  + 3u;
    TF_R4(17, 29, 16, 24)  x0 += k1;  x1 += ks2 + 4u;
    TF_R4(13, 15, 26, 6)   x0 += ks2; x1 += k0  + 5u;
#undef TF_R4
#undef TF_ROT
    *o0 = x0; *o1 = x1;
}

// exact JAX gumbel for element idx under jax_threefry_partitionable:
// bits = o0 ^ o1 of threefry(key, (0, idx))
__device__ __forceinline__ float gumbel_exact(uint32_t k0, uint32_t k1, uint32_t idx)
{
    uint32_t y0, y1;
    tf2x32(k0, k1, 0u, idx, &y0, &y1);
    uint32_t bits = y0 ^ y1;
    float u = __uint_as_float((bits >> 9) | 0x3f800000u) - 1.0f;
    const float minv = 1e-6f;
    const float span = 0.999999f - 1e-6f;   // fp32, same as JAX
    float vv = fmaxf(minv, u * span + minv);
    // fp64 log: immune to fast-math logf
    return (float)(-log(-log((double)vv)));
}

// ---------------------------------------------------------------------------
// MLP layer accumulate: acc[s] = bias[t] + sum_e in[s][e] * W[e*kE + t]
// (weights coalesced from global; activations broadcast from smem)
// ---------------------------------------------------------------------------
__device__ __forceinline__ void mlp_acc(const float (*in)[kE],
                                        const float* __restrict__ W,
                                        const float* __restrict__ bias,
                                        int t, float* acc)
{
    float bv = bias[t];
    #pragma unroll
    for (int s = 0; s < TS; s++) acc[s] = bv;
    const float* w = W + t;
    for (int e = 0; e < kE; e += 4) {
        float w0 = w[(size_t)(e + 0) * kE];
        float w1 = w[(size_t)(e + 1) * kE];
        float w2 = w[(size_t)(e + 2) * kE];
        float w3 = w[(size_t)(e + 3) * kE];
        #pragma unroll
        for (int s = 0; s < TS; s++) {
            float4 sv = *(const float4*)&in[s][e];
            acc[s] = fmaf(sv.x, w0, acc[s]);
            acc[s] = fmaf(sv.y, w1, acc[s]);
            acc[s] = fmaf(sv.z, w2, acc[s]);
            acc[s] = fmaf(sv.w, w3, acc[s]);
        }
    }
}

// ---------------------------------------------------------------------------
// Embed GEMM: C = A[MxK] @ W[KxN] + bias, copy to C2. Also zeroes g_cnt.
// BM=32, BN=64, BK=16, 256 threads.
// ---------------------------------------------------------------------------
__global__ void embed_kernel(const float* __restrict__ A,
                             const float* __restrict__ W,
                             const float* __restrict__ bias,
                             float* __restrict__ C,
                             float* __restrict__ C2,
                             int M, int K, int Nn)
{
    const int t = threadIdx.x;
    if (blockIdx.x == 0 && blockIdx.y == 0) {
        int* c = &g_cnt[0][0];
        for (int i = t; i < (kJ + 1) * kNB; i += 256) c[i] = 0;
    }
    __shared__ float As[16][33];
    __shared__ float Ws[16][64];
    const int tx = t & 15;
    const int ty = t >> 4;
    const int row0 = blockIdx.y * 32;
    const int col0 = blockIdx.x * 64;
    float acc[2][4] = {{0.f,0.f,0.f,0.f},{0.f,0.f,0.f,0.f}};

    for (int k0 = 0; k0 < K; k0 += 16) {
        if (t < 128) {
            int r  = t >> 2;
            int kk = (t & 3) * 4;
            float4 v = *(const float4*)(A + (size_t)(row0 + r) * K + k0 + kk);
            As[kk + 0][r] = v.x; As[kk + 1][r] = v.y;
            As[kk + 2][r] = v.z; As[kk + 3][r] = v.w;
        }
        {
            int kk = t >> 4;
            int c  = (t & 15) * 4;
            *(float4*)&Ws[kk][c] =
                *(const float4*)(W + (size_t)(k0 + kk) * Nn + col0 + c);
        }
        __syncthreads();
        #pragma unroll
        for (int kk = 0; kk < 16; kk++) {
            float a0 = As[kk][ty * 2 + 0];
            float a1 = As[kk][ty * 2 + 1];
            float4 b4 = *(const float4*)&Ws[kk][tx * 4];
            acc[0][0] = fmaf(a0, b4.x, acc[0][0]);
            acc[0][1] = fmaf(a0, b4.y, acc[0][1]);
            acc[0][2] = fmaf(a0, b4.z, acc[0][2]);
            acc[0][3] = fmaf(a0, b4.w, acc[0][3]);
            acc[1][0] = fmaf(a1, b4.x, acc[1][0]);
            acc[1][1] = fmaf(a1, b4.y, acc[1][1]);
            acc[1][2] = fmaf(a1, b4.z, acc[1][2]);
            acc[1][3] = fmaf(a1, b4.w, acc[1][3]);
        }
        __syncthreads();
    }

    float4 bv = *(const float4*)(bias + col0 + tx * 4);
    #pragma unroll
    for (int i = 0; i < 2; i++) {
        float4 o;
        o.x = acc[i][0] + bv.x; o.y = acc[i][1] + bv.y;
        o.z = acc[i][2] + bv.z; o.w = acc[i][3] + bv.w;
        size_t off = (size_t)(row0 + ty * 2 + i) * Nn + col0 + tx * 4;
        *(float4*)(C + off)  = o;
        *(float4*)(C2 + off) = o;
    }
}

// ---------------------------------------------------------------------------
// addr0: initial address for all samples.
//   h = relu(state @ at0_W1 + b1); logits = h @ at0_W2 + b2 (+gumbel key0);
//   argmax digits -> n; done=0; route into list[0].
// grid 128 CTAs x 256 threads, 8 samples per CTA.
// ---------------------------------------------------------------------------
__global__ void addr0_kernel(const float* __restrict__ aW1,
                             const float* __restrict__ ab1,
                             const float* __restrict__ aW2,
                             const float* __restrict__ ab2,
                             uint32_t k0, uint32_t k1)
{
    __shared__ float sA[TS][kE];
    __shared__ float sB[TS][kE];
    __shared__ float sW2T[KOUT][kE];
    const int t = threadIdx.x, wid = t >> 5, lane = t & 31;
    const int b0 = blockIdx.x * TS;
    const unsigned fm = 0xffffffffu;

    for (int i = t; i < kE * KOUT; i += 256)
        sW2T[i % KOUT][i / KOUT] = aW2[i];
    #pragma unroll
    for (int s = 0; s < TS; s++) sA[s][t] = g_state[(size_t)(b0 + s) * kE + t];
    __syncthreads();

    {   // h = relu(state @ aW1 + ab1)
        float acc[TS];
        mlp_acc(sA, aW1, ab1, t, acc);
        #pragma unroll
        for (int s = 0; s < TS; s++) sB[s][t] = fmaxf(acc[s], 0.f);
    }
    __syncthreads();

    // logits per warp (warp wid handles sample b0+wid)
    const int b = b0 + wid;
    float hr[kE / 32];
    #pragma unroll
    for (int q = 0; q < kE / 32; q++) hr[q] = sB[wid][lane + 32 * q];
    float zmine = 0.f;
    #pragma unroll
    for (int k = 0; k < KOUT; k++) {
        float sum = 0.f;
        #pragma unroll
        for (int q = 0; q < kE / 32; q++)
            sum = fmaf(hr[q], sW2T[k][lane + 32 * q], sum);
        #pragma unroll
        for (int o = 16; o; o >>= 1) sum += __shfl_down_sync(fm, sum, o);
        float v = __shfl_sync(fm, sum, 0);
        if (lane == k) zmine = v + ab2[k];
    }
    if (lane < KOUT) zmine += gumbel_exact(k0, k1, (uint32_t)(b * KOUT + lane));
    float zv[KOUT];
    #pragma unroll
    for (int k = 0; k < KOUT; k++) zv[k] = __shfl_sync(fm, zmine, k);

    if (lane == 0) {
        int n_val = 0;
        #pragma unroll
        for (int d = 0; d < kAD; d++) {
            int bi = 0; float bvv = zv[d * kBR];
            #pragma unroll
            for (int c = 1; c < kBR; c++) {
                float x = zv[d * kBR + c];
                if (x > bvv) { bvv = x; bi = c; }
            }
            n_val = n_val * kBR + bi;
        }
        g_done[b] = 0;
        int pos = atomicAdd(&g_cnt[0][n_val], 1);
        g_list[0][n_val][pos] = b;
    }
}

// ---------------------------------------------------------------------------
// Fused jump: consume list[jin] (grouped by block n = blockIdx.x):
//   norm = ||state||; h1 = relu(state@W1[n]+b1[n]); h2 = relu(h1@W2[n]+b2[n]);
//   new_state = h2/(norm+1e-6); commit to g_state if active;
//   h3 = relu(new_state@aW1+ab1); logits+gumbel(key)+argmax -> n_val;
//   done update; route into list[jout] (frozen samples keep block n).
// grid (64, 16), 256 threads, TS=8 samples per tile.
// ---------------------------------------------------------------------------
__global__ void jump_kernel(const float* __restrict__ W1,
                            const float* __restrict__ b1,
                            const float* __restrict__ W2,
                            const float* __restrict__ b2,
                            const float* __restrict__ aW1,
                            const float* __restrict__ ab1,
                            const float* __restrict__ aW2,
                            const float* __restrict__ ab2,
                            uint32_t k0, uint32_t k1, int jin, int jout)
{
    const int n = blockIdx.x;
    const int cnt = g_cnt[jin][n];
    if ((int)(blockIdx.y * TS) >= cnt) return;

    __shared__ float sA[TS][kE];
    __shared__ float sB[TS][kE];
    __shared__ float sW2T[KOUT][kE];
    __shared__ float snorm[TS];
    __shared__ int   sids[TS];
    __shared__ int   sdone[TS];
    const int t = threadIdx.x, wid = t >> 5, lane = t & 31;
    const unsigned fm = 0xffffffffu;
    const float* bW1 = W1 + (size_t)n * kE * kE;
    const float* bW2 = W2 + (size_t)n * kE * kE;

    for (int i = t; i < kE * KOUT; i += 256)
        sW2T[i % KOUT][i / KOUT] = aW2[i];

    for (int tile = blockIdx.y; tile * TS < cnt; tile += gridDim.y) {
        const int m = min(TS, cnt - tile * TS);
        if (t < TS) {
            int id = (t < m) ? g_list[jin][n][tile * TS + t] : -1;
            sids[t]  = id;
            sdone[t] = (id >= 0) ? g_done[id] : 1;
        }
        __syncthreads();
        #pragma unroll
        for (int s = 0; s < TS; s++)
            sA[s][t] = (s < m) ? g_state[(size_t)sids[s] * kE + t] : 0.f;
        __syncthreads();
        {   // norms: warp wid -> sample wid
            float v = 0.f;
            #pragma unroll
            for (int q = 0; q < kE / 32; q++) {
                float x = sA[wid][lane + 32 * q];
                v = fmaf(x, x, v);
            }
            #pragma unroll
            for (int o = 16; o; o >>= 1) v += __shfl_down_sync(fm, v, o);
            if (lane == 0) snorm[wid] = sqrtf(v) + 1e-6f;
        }
        __syncthreads();
        {   // layer 1
            float acc[TS];
            mlp_acc(sA, bW1, b1 + n * kE, t, acc);
            #pragma unroll
            for (int s = 0; s < TS; s++) sB[s][t] = fmaxf(acc[s], 0.f);
        }
        __syncthreads();
        {   // layer 2 + normalize + commit
            float acc[TS];
            mlp_acc(sB, bW2, b2 + n * kE, t, acc);
            __syncthreads();   // sA reads done by all before overwrite
            #pragma unroll
            for (int s = 0; s < TS; s++) {
                float val = fmaxf(acc[s], 0.f) / snorm[s];
                sA[s][t] = val;
                if (s < m && !sdone[s])
                    g_state[(size_t)sids[s] * kE + t] = val;
            }
        }
        __syncthreads();
        {   // layer 3: address hidden
            float acc[TS];
            mlp_acc(sA, aW1, ab1, t, acc);
            #pragma unroll
            for (int s = 0; s < TS; s++) sB[s][t] = fmaxf(acc[s], 0.f);
        }
        __syncthreads();

        // logits + gumbel + argmax + route (warp wid -> sample wid)
        if (wid < m) {
            const int b = sids[wid];
            float hr[kE / 32];
            #pragma unroll
            for (int q = 0; q < kE / 32; q++) hr[q] = sB[wid][lane + 32 * q];
            float zmine = 0.f;
            #pragma unroll
            for (int k = 0; k < KOUT; k++) {
                float sum = 0.f;
                #pragma unroll
                for (int q = 0; q < kE / 32; q++)
                    sum = fmaf(hr[q], sW2T[k][lane + 32 * q], sum);
                #pragma unroll
                for (int o = 16; o; o >>= 1) sum += __shfl_down_sync(fm, sum, o);
                float v = __shfl_sync(fm, sum, 0);
                if (lane == k) zmine = v + ab2[k];
            }
            if (lane < KOUT)
                zmine += gumbel_exact(k0, k1, (uint32_t)(b * KOUT + lane));
            float zv[KOUT];
            #pragma unroll
            for (int k = 0; k < KOUT; k++) zv[k] = __shfl_sync(fm, zmine, k);

            if (lane == 0) {
                int n_val = 0;
                #pragma unroll
                for (int d = 0; d < kAD; d++) {
                    int bi = 0; float bvv = zv[d * kBR];
                    #pragma unroll
                    for (int c = 1; c < kBR; c++) {
                        float x = zv[d * kBR + c];
                        if (x > bvv) { bvv = x; bi = c; }
                    }
                    n_val = n_val * kBR + bi;
                }
                int done_pre = sdone[wid];
                int rn = done_pre ? n : n_val;        // frozen samples keep block n
                if (!done_pre && n_val == 0) g_done[b] = 1;
                int pos = atomicAdd(&g_cnt[jout][rn], 1);
                g_list[jout][rn][pos] = b;
            }
        }
        __syncthreads();
    }
}

// ---------------------------------------------------------------------------
// Fused final: consume list[kJ]:
//   fin = relu(h1,h2 MLP)/norm + initial_state;
//   h = relu(fin @ out_W1 + out_b1); out = h @ out_W2 + out_b2.
// ---------------------------------------------------------------------------
__global__ void final_kernel(const float* __restrict__ W1,
                             const float* __restrict__ b1,
                             const float* __restrict__ W2,
                             const float* __restrict__ b2,
                             const float* __restrict__ oW1,
                             const float* __restrict__ ob1,
                             const float* __restrict__ oW2,
                             const float* __restrict__ ob2,
                             float* __restrict__ outp)
{
    const int n = blockIdx.x;
    const int cnt = g_cnt[kJ][n];
    if ((int)(blockIdx.y * TS) >= cnt) return;

    __shared__ float sA[TS][kE];
    __shared__ float sB[TS][kE];
    __shared__ float sW2T[kC][kE];
    __shared__ float snorm[TS];
    __shared__ int   sids[TS];
    const int t = threadIdx.x, wid = t >> 5, lane = t & 31;
    const unsigned fm = 0xffffffffu;
    const float* bW1 = W1 + (size_t)n * kE * kE;
    const float* bW2 = W2 + (size_t)n * kE * kE;

    for (int i = t; i < kE * kC; i += 256)
        sW2T[i % kC][i / kC] = oW2[i];

    for (int tile = blockIdx.y; tile * TS < cnt; tile += gridDim.y) {
        const int m = min(TS, cnt - tile * TS);
        if (t < TS) sids[t] = (t < m) ? g_list[kJ][n][tile * TS + t] : -1;
        __syncthreads();
        #pragma unroll
        for (int s = 0; s < TS; s++)
            sA[s][t] = (s < m) ? g_state[(size_t)sids[s] * kE + t] : 0.f;
        __syncthreads();
        {
            float v = 0.f;
            #pragma unroll
            for (int q = 0; q < kE / 32; q++) {
                float x = sA[wid][lane + 32 * q];
                v = fmaf(x, x, v);
            }
            #pragma unroll
            for (int o = 16; o; o >>= 1) v += __shfl_down_sync(fm, v, o);
            if (lane == 0) snorm[wid] = sqrtf(v) + 1e-6f;
        }
        __syncthreads();
        {   // layer 1
            float acc[TS];
            mlp_acc(sA, bW1, b1 + n * kE, t, acc);
            #pragma unroll
            for (int s = 0; s < TS; s++) sB[s][t] = fmaxf(acc[s], 0.f);
        }
        __syncthreads();
        {   // layer 2 + normalize + residual
            float acc[TS];
            mlp_acc(sB, bW2, b2 + n * kE, t, acc);
            __syncthreads();
            #pragma unroll
            for (int s = 0; s < TS; s++) {
                float val = fmaxf(acc[s], 0.f) / snorm[s];
                if (s < m) val += g_init[(size_t)sids[s] * kE + t];
                sA[s][t] = val;
            }
        }
        __syncthreads();
        {   // out hidden
            float acc[TS];
            mlp_acc(sA, oW1, ob1, t, acc);
            #pragma unroll
            for (int s = 0; s < TS; s++) sB[s][t] = fmaxf(acc[s], 0.f);
        }
        __syncthreads();

        if (wid < m) {
            const int b = sids[wid];
            float hr[kE / 32];
            #pragma unroll
            for (int q = 0; q < kE / 32; q++) hr[q] = sB[wid][lane + 32 * q];
            #pragma unroll
            for (int c = 0; c < kC; c++) {
                float sum = 0.f;
                #pragma unroll
                for (int q = 0; q < kE / 32; q++)
                    sum = fmaf(hr[q], sW2T[c][lane + 32 * q], sum);
                #pragma unroll
                for (int o = 16; o; o >>= 1) sum += __shfl_down_sync(fm, sum, o);
                if (lane == 0) outp[(size_t)b * kC + c] = sum + ob2[c];
            }
        }
        __syncthreads();
    }
}

// ---------------------------------------------------------------------------
// Launch: 7 kernels total
// ---------------------------------------------------------------------------
extern "C" void kernel_launch(void* const* d_in, const int* in_sizes, int n_in,
                              void* d_out, int out_size)
{
    (void)in_sizes; (void)n_in; (void)out_size;
    const float* x      = (const float*)d_in[0];
    const float* W_emb  = (const float*)d_in[1];
    const float* b_emb  = (const float*)d_in[2];
    const float* st_W1  = (const float*)d_in[3];
    const float* st_b1  = (const float*)d_in[4];
    const float* st_W2  = (const float*)d_in[5];
    const float* st_b2  = (const float*)d_in[6];
    const float* at0_W1 = (const float*)d_in[7];
    const float* at0_b1 = (const float*)d_in[8];
    const float* at0_W2 = (const float*)d_in[9];
    const float* at0_b2 = (const float*)d_in[10];
    const float* out_W1 = (const float*)d_in[11];
    const float* out_b1 = (const float*)d_in[12];
    const float* out_W2 = (const float*)d_in[13];
    const float* out_b2 = (const float*)d_in[14];
    float* out = (float*)d_out;

    // JAX keys: key_j = threefry((0,42), (0,j))  [fold_in(_GKEY, j)]
    uint32_t kk0[kJ + 1], kk1[kJ + 1];
    for (int j = 0; j <= kJ; j++)
        tf2x32(0u, 42u, 0u, (uint32_t)j, &kk0[j], &kk1[j]);

    float *p_state, *p_init;
    cudaGetSymbolAddress((void**)&p_state, g_state);
    cudaGetSymbolAddress((void**)&p_init,  g_init);

    // 1. embed (also zeroes routing counters for this replay)
    embed_kernel<<<dim3(kE / 64, kB / 32), 256>>>(x, W_emb, b_emb,
                                                  p_state, p_init, kB, kIN, kE);
    // 2. initial address
    addr0_kernel<<<kB / TS, 256>>>(at0_W1, at0_b1, at0_W2, at0_b2,
                                   kk0[0], kk1[0]);
    // 3-6. fused jumps
    for (int i = 0; i < kJ; i++)
        jump_kernel<<<dim3(kNB, 16), 256>>>(st_W1, st_b1, st_W2, st_b2,
                                            at0_W1, at0_b1, at0_W2, at0_b2,
                                            kk0[i + 1], kk1[i + 1], i, i + 1);
    // 7. fused final block step + output head
    final_kernel<<<dim3(kNB, 16), 256>>>(st_W1, st_b1, st_W2, st_b2,
                                         out_W1, out_b1, out_W2, out_b2, out);
}